// round 3
// baseline (speedup 1.0000x reference)
#include <cuda_runtime.h>
#include <cstdint>

// YOLOv1 loss — single fused kernel.
// TMA bulk copies (cp.async.bulk + mbarrier) feed a 2-stage smem pipeline;
// per-cell compute; deterministic tree reduction; ticket finalize.

#define TPB   128
#define TILE  128
#define TILE_BYTES  (TILE * 30 * 4)        // 15360 per tensor per tile
#define STAGE_BYTES (2 * TILE_BYTES)       // 30720 (pred + target)
#define NSTAGE 2
#define SMEM_BYTES (NSTAGE * STAGE_BYTES)  // 61440
#define GRID_MAX 1024

__device__ float g_partials[GRID_MAX * 5];
__device__ unsigned int g_ticket = 0;

__device__ __forceinline__ uint32_t smem_u32(const void* p) {
    uint32_t a;
    asm("{ .reg .u64 t; cvta.to.shared.u64 t, %1; cvt.u32.u64 %0, t; }"
        : "=r"(a) : "l"(p));
    return a;
}

__device__ __forceinline__ void mbar_init(uint32_t mbar, uint32_t cnt) {
    asm volatile("mbarrier.init.shared.b64 [%0], %1;" :: "r"(mbar), "r"(cnt) : "memory");
}

__device__ __forceinline__ void mbar_expect_tx(uint32_t mbar, uint32_t bytes) {
    asm volatile("mbarrier.arrive.expect_tx.shared.b64 _, [%0], %1;"
                 :: "r"(mbar), "r"(bytes) : "memory");
}

__device__ __forceinline__ void mbar_wait(uint32_t mbar, uint32_t parity) {
    uint32_t done;
    asm volatile(
        "{\n\t.reg .pred p;\n\t"
        "mbarrier.try_wait.parity.acquire.cta.shared::cta.b64 p, [%1], %2;\n\t"
        "selp.b32 %0, 1, 0, p;\n\t}"
        : "=r"(done) : "r"(mbar), "r"(parity) : "memory");
    if (!done) {
        asm volatile(
            "{\n\t.reg .pred P1;\n\t"
            "W_%=:\n\t"
            "mbarrier.try_wait.parity.acquire.cta.shared::cta.b64 P1, [%0], %1, 0x989680;\n\t"
            "@P1 bra.uni D_%=;\n\t"
            "bra.uni W_%=;\n\t"
            "D_%=:\n\t}"
            :: "r"(mbar), "r"(parity) : "memory");
    }
}

__device__ __forceinline__ void bulk_g2s(uint32_t sdst, const void* gsrc,
                                         uint32_t bytes, uint32_t mbar) {
    asm volatile(
        "cp.async.bulk.shared::cluster.global.mbarrier::complete_tx::bytes "
        "[%0], [%1], %2, [%3];"
        :: "r"(sdst), "l"(gsrc), "r"(bytes), "r"(mbar) : "memory");
}

__device__ __forceinline__ float iou_fn(float bx, float by, float bw, float bh,
                                        float tx, float ty, float tw, float th)
{
    float ax1 = bx - bw * 0.5f, ay1 = by - bh * 0.5f;
    float ax2 = bx + bw * 0.5f, ay2 = by + bh * 0.5f;
    float cx1 = tx - tw * 0.5f, cy1 = ty - th * 0.5f;
    float cx2 = tx + tw * 0.5f, cy2 = ty + th * 0.5f;
    float iw = fmaxf(fminf(ax2, cx2) - fmaxf(ax1, cx1), 0.0f);
    float ih = fmaxf(fminf(ay2, cy2) - fmaxf(ay1, cy1), 0.0f);
    float inter = iw * ih;
    float uni = bw * bh + tw * th - inter;
    return inter / fmaxf(uni, 1e-10f);
}

// Per-cell loss update. P = 30 pred floats, T = 30 target floats.
__device__ __forceinline__ void cell_update(const float* __restrict__ P,
                                            const float* __restrict__ T,
                                            float& a0, float& a1, float& a2,
                                            float& a3, float& a4)
{
    float t4v  = T[4];
    float objf = (t4v == 1.0f) ? 1.0f : 0.0f;
    float noobjf = 1.0f - objf;

    float tx = T[0], ty = T[1], tw = T[2], th = T[3];
    float i0 = iou_fn(P[0], P[1], P[2], P[3], tx, ty, tw, th);
    float i1 = iou_fn(P[5], P[6], P[7], P[8], tx, ty, tw, th);

    bool b0 = (i0 > i1);   // ties -> box 1 (matches jnp.where)
    float wx = b0 ? P[0] : P[5];
    float wy = b0 ? P[1] : P[6];
    float ww = b0 ? P[2] : P[7];
    float wh = b0 ? P[3] : P[8];
    float wc = b0 ? P[4] : P[9];
    float wiou = fmaxf(i0, i1);

    float dx = wx - tx, dy = wy - ty;
    float dw = sqrtf(ww) - sqrtf(tw);
    float dh = sqrtf(wh) - sqrtf(th);
    a0 += (dx * dx + dy * dy + dw * dw + dh * dh) * objf;

    float dc = wc - wiou;
    a1 += dc * dc * objf;

    float d4 = P[4] - t4v;
    float d9 = P[9] - T[9];
    a2 += (d4 * d4 + d9 * d9) * noobjf;

    float m = -1e30f;
    #pragma unroll
    for (int c = 0; c < 20; c++) m = fmaxf(m, P[10 + c]);
    float sum = 0.0f;
    #pragma unroll
    for (int c = 0; c < 20; c++) sum += __expf(P[10 + c] - m);
    float tm = -1e30f; int targc = 0;
    #pragma unroll
    for (int c = 0; c < 20; c++) {
        float v = T[10 + c];
        if (v > tm) { tm = v; targc = c; }  // first-occurrence argmax
    }
    float ce = m + __logf(sum) - P[10 + targc];
    a3 += ce * objf;
    a4 += objf;
}

extern __shared__ float dynbuf[];   // NSTAGE stages of STAGE_BYTES

__global__ __launch_bounds__(TPB)
void yolo_fused_kernel(const float* __restrict__ pred,
                       const float* __restrict__ target,
                       int n_cells, float invB,
                       float* __restrict__ out)
{
    const int tid = threadIdx.x;
    const int nb  = gridDim.x;
    const int ntiles = n_cells / TILE;          // full tiles
    const int rem    = n_cells - ntiles * TILE; // leftover cells

    __shared__ unsigned long long mbar_store[NSTAGE];
    __shared__ float sred[5][TPB / 32];
    __shared__ int amLast;

    const uint32_t mb = smem_u32(&mbar_store[0]);
    const uint32_t sbase = smem_u32(dynbuf);

    if (tid == 0) {
        mbar_init(mb,     1);
        mbar_init(mb + 8, 1);
        asm volatile("fence.proxy.async.shared::cta;" ::: "memory");
    }
    __syncthreads();

    float acc0 = 0.f, acc1 = 0.f, acc2 = 0.f, acc3 = 0.f, acc4 = 0.f;

    // Remainder cells: block 0 handles directly from global (tiny).
    if (rem && blockIdx.x == 0 && tid < rem) {
        long long c0 = (long long)ntiles * TILE + tid;
        float Pv[30], Tv[30];
        const float* pg = pred   + c0 * 30;
        const float* tg = target + c0 * 30;
        #pragma unroll
        for (int k = 0; k < 30; k++) { Pv[k] = __ldg(pg + k); Tv[k] = __ldg(tg + k); }
        cell_update(Pv, Tv, acc0, acc1, acc2, acc3, acc4);
    }

    // ---- pipelined full tiles ----
    auto issue = [&](int t, int s) {
        if (tid == 0) {
            const char* pg = (const char*)pred   + (long long)t * TILE_BYTES;
            const char* tg = (const char*)target + (long long)t * TILE_BYTES;
            uint32_t dst = sbase + (uint32_t)s * STAGE_BYTES;
            mbar_expect_tx(mb + 8u * s, STAGE_BYTES);
            bulk_g2s(dst,              pg, TILE_BYTES, mb + 8u * s);
            bulk_g2s(dst + TILE_BYTES, tg, TILE_BYTES, mb + 8u * s);
        }
    };

    int t = blockIdx.x;
    if (t < ntiles)      issue(t, 0);
    if (t + nb < ntiles) issue(t + nb, 1);

    int it = 0;
    for (; t < ntiles; t += nb, ++it) {
        int s = it & 1;
        mbar_wait(mb + 8u * s, (it >> 1) & 1);

        const float* stage = dynbuf + (size_t)s * (STAGE_BYTES / 4);
        const float2* P2 = (const float2*)(stage + tid * 30);
        const float2* T2 = (const float2*)(stage + TILE_BYTES / 4 + tid * 30);
        float Pv[30], Tv[30];
        #pragma unroll
        for (int k = 0; k < 15; k++) {
            float2 v = P2[k]; Pv[2 * k] = v.x; Pv[2 * k + 1] = v.y;
            float2 w = T2[k]; Tv[2 * k] = w.x; Tv[2 * k + 1] = w.y;
        }
        cell_update(Pv, Tv, acc0, acc1, acc2, acc3, acc4);

        __syncthreads();               // stage s fully consumed
        if (t + 2 * nb < ntiles) issue(t + 2 * nb, s);
    }

    // ---- deterministic in-block reduction ----
    const unsigned mask = 0xffffffffu;
    #pragma unroll
    for (int off = 16; off; off >>= 1) {
        acc0 += __shfl_down_sync(mask, acc0, off);
        acc1 += __shfl_down_sync(mask, acc1, off);
        acc2 += __shfl_down_sync(mask, acc2, off);
        acc3 += __shfl_down_sync(mask, acc3, off);
        acc4 += __shfl_down_sync(mask, acc4, off);
    }
    int lane = tid & 31, w = tid >> 5;
    if (lane == 0) {
        sred[0][w] = acc0; sred[1][w] = acc1; sred[2][w] = acc2;
        sred[3][w] = acc3; sred[4][w] = acc4;
    }
    __syncthreads();
    if (tid == 0) {
        float r0 = 0.f, r1 = 0.f, r2 = 0.f, r3 = 0.f, r4 = 0.f;
        #pragma unroll
        for (int i = 0; i < TPB / 32; i++) {
            r0 += sred[0][i]; r1 += sred[1][i]; r2 += sred[2][i];
            r3 += sred[3][i]; r4 += sred[4][i];
        }
        g_partials[blockIdx.x * 5 + 0] = r0;
        g_partials[blockIdx.x * 5 + 1] = r1;
        g_partials[blockIdx.x * 5 + 2] = r2;
        g_partials[blockIdx.x * 5 + 3] = r3;
        g_partials[blockIdx.x * 5 + 4] = r4;
    }

    // ---- ticket: last block finalizes ----
    __threadfence();
    __syncthreads();
    if (tid == 0) {
        unsigned tk = atomicAdd(&g_ticket, 1u);
        amLast = (tk == (unsigned)(nb - 1));
    }
    __syncthreads();

    if (amLast) {
        float a0 = 0.f, a1 = 0.f, a2 = 0.f, a3 = 0.f, a4 = 0.f;
        for (int j = tid; j < nb; j += TPB) {
            a0 += g_partials[j * 5 + 0];
            a1 += g_partials[j * 5 + 1];
            a2 += g_partials[j * 5 + 2];
            a3 += g_partials[j * 5 + 3];
            a4 += g_partials[j * 5 + 4];
        }
        #pragma unroll
        for (int off = 16; off; off >>= 1) {
            a0 += __shfl_down_sync(mask, a0, off);
            a1 += __shfl_down_sync(mask, a1, off);
            a2 += __shfl_down_sync(mask, a2, off);
            a3 += __shfl_down_sync(mask, a3, off);
            a4 += __shfl_down_sync(mask, a4, off);
        }
        if (lane == 0) {
            sred[0][w] = a0; sred[1][w] = a1; sred[2][w] = a2;
            sred[3][w] = a3; sred[4][w] = a4;
        }
        __syncthreads();
        if (tid == 0) {
            float loc = 0.f, cobj = 0.f, cno = 0.f, ce = 0.f, nobj = 0.f;
            #pragma unroll
            for (int i = 0; i < TPB / 32; i++) {
                loc += sred[0][i]; cobj += sred[1][i]; cno += sred[2][i];
                ce  += sred[3][i]; nobj += sred[4][i];
            }
            float n   = fmaxf(nobj, 1.0f);
            float cls = ce / n;
            out[0] = (5.0f * loc + cobj + 0.5f * cno + cls) * invB;
            out[1] = loc;
            out[2] = cobj;
            out[3] = cno;
            out[4] = cls;
            __threadfence();
            g_ticket = 0;   // reset for next graph replay
        }
    }
}

extern "C" void kernel_launch(void* const* d_in, const int* in_sizes, int n_in,
                              void* d_out, int out_size)
{
    const float* pred   = (const float*)d_in[0];
    const float* target = (const float*)d_in[1];
    int n_elems = in_sizes[0];
    int n_cells = n_elems / 30;

    static bool configured = false;
    if (!configured) {
        cudaFuncSetAttribute(yolo_fused_kernel,
                             cudaFuncAttributeMaxDynamicSharedMemorySize,
                             SMEM_BYTES);
        configured = true;
    }

    int ntiles = (n_cells + TILE - 1) / TILE;
    int grid = 444;                        // 148 SMs x 3 CTAs @ 61.4 KB smem
    if (grid > ntiles) grid = ntiles;
    if (grid < 1) grid = 1;
    if (grid > GRID_MAX) grid = GRID_MAX;

    float invB = 49.0f / (float)n_cells;   // B = n_cells / 49

    yolo_fused_kernel<<<grid, TPB, SMEM_BYTES>>>(pred, target, n_cells, invB,
                                                 (float*)d_out);
}